// round 2
// baseline (speedup 1.0000x reference)
#include <cuda_runtime.h>
#include <cstdint>

// Problem constants (fixed): N=8, T=200, U=100, D=512, V=500
#define JN 8
#define JT 200
#define JU 100
#define JD 512
#define JV 500
#define JM (JN * JT * JU)   // 160000

// ---------------------------------------------------------------------------
// Scratch: tf32-rounded tanh(enc+dec), computed once. 160000*512*4B = 327.7 MB.
// __device__ global array = sanctioned scratch (no cudaMalloc allowed).
// ---------------------------------------------------------------------------
__device__ float g_A[(size_t)JM * JD];

__device__ __forceinline__ float fast_tanh(float x) {
    // Exact identity tanh(x) = 1 - 2/(e^{2x}+1); numerically ~1e-7 abs err.
    // Saturates correctly: e->inf => 1, e->0 => -1.
    float e = __expf(2.0f * x);
    return 1.0f - __fdividef(2.0f, e + 1.0f);
}

__device__ __forceinline__ unsigned f2tf32(float f) {
    unsigned u;
    asm("cvt.rna.tf32.f32 %0, %1;" : "=r"(u) : "f"(f));
    return u;
}

// ============================ Pass 1: tanh =================================
__global__ __launch_bounds__(256)
void tanh_pass(const float* __restrict__ enc, const float* __restrict__ dec) {
    int idx = blockIdx.x * blockDim.x + threadIdx.x;  // one float4 of A
    const int TOT = JM * (JD / 4);                    // 20,480,000
    if (idx >= TOT) return;
    int k4 = idx & (JD / 4 - 1);                      // JD/4 = 128
    int m  = idx >> 7;
    int n = m / (JT * JU);
    int r = m % (JT * JU);
    int t = r / JU;
    int u = r % JU;
    const float4 e = *(const float4*)(enc + (size_t)(n * JT + t) * JD + k4 * 4);
    const float4 d = *(const float4*)(dec + (size_t)(n * JU + u) * JD + k4 * 4);
    uint4 o;
    o.x = f2tf32(fast_tanh(e.x + d.x));
    o.y = f2tf32(fast_tanh(e.y + d.y));
    o.z = f2tf32(fast_tanh(e.z + d.z));
    o.w = f2tf32(fast_tanh(e.w + d.w));
    *(uint4*)(g_A + (size_t)m * JD + k4 * 4) = o;
}

// ============================ Pass 2: tf32 GEMM ============================
// C[M,V] = A[M,K] * W^T + b.  W is (V,D) row-major == K-col-major B operand.
// Block tile 128x128, BK=16, 256 threads, 8 warps in 2(M) x 4(N).
// Warp tile 64x32 = 4x4 m16n8k8 mma tiles. cp.async 2-stage pipeline.

#define BK  16
#define PK  20   // smem row stride in floats: (20*g + tg) % 32 covers all banks

__device__ __forceinline__ void cpa16(void* dst, const void* src) {
    unsigned d = (unsigned)__cvta_generic_to_shared(dst);
    asm volatile("cp.async.cg.shared.global [%0], [%1], 16;\n" :: "r"(d), "l"(src));
}

__global__ __launch_bounds__(256)
void joiner_gemm(const float* __restrict__ W, const float* __restrict__ bias,
                 float* __restrict__ out) {
    __shared__ float As[2][128 * PK];
    __shared__ float Bs[2][128 * PK];

    const int tid  = threadIdx.x;
    const int lane = tid & 31;
    const int wid  = tid >> 5;
    const int g    = lane >> 2;   // groupID (0..7)
    const int tg   = lane & 3;    // thread in group (0..3)
    const int wm   = wid & 1;     // warp row (0..1) -> 64 M each
    const int wn   = wid >> 1;    // warp col (0..3) -> 32 N each

    const int m0 = blockIdx.y * 128;
    const int v0 = blockIdx.x * 128;

    // ---- global load roles: thread -> (row lrow & lrow+64, k-float4 kg) ----
    const int kg   = tid & 3;
    const int lrow = tid >> 2;    // 0..63
    const float* gA0 = g_A + (size_t)(m0 + lrow) * JD + kg * 4;
    const float* gA1 = gA0 + (size_t)64 * JD;
    int vr0 = v0 + lrow;      if (vr0 > JV - 1) vr0 = JV - 1;   // clamp (dup rows unused)
    int vr1 = v0 + lrow + 64; if (vr1 > JV - 1) vr1 = JV - 1;
    const float* gB0 = W + (size_t)vr0 * JD + kg * 4;
    const float* gB1 = W + (size_t)vr1 * JD + kg * 4;

    float acc[4][4][4];
    #pragma unroll
    for (int mt = 0; mt < 4; mt++)
        #pragma unroll
        for (int nt = 0; nt < 4; nt++)
            #pragma unroll
            for (int i = 0; i < 4; i++) acc[mt][nt][i] = 0.0f;

    // prologue: stage 0
    {
        cpa16(&As[0][lrow * PK + kg * 4],        gA0);
        cpa16(&As[0][(lrow + 64) * PK + kg * 4], gA1);
        cpa16(&Bs[0][lrow * PK + kg * 4],        gB0);
        cpa16(&Bs[0][(lrow + 64) * PK + kg * 4], gB1);
        asm volatile("cp.async.commit_group;\n");
    }

    const int NIT = JD / BK;   // 32
    #pragma unroll 1
    for (int it = 0; it < NIT; ++it) {
        const int buf = it & 1;
        if (it + 1 < NIT) {
            const int nb = buf ^ 1;
            const int ko = (it + 1) * BK;
            cpa16(&As[nb][lrow * PK + kg * 4],        gA0 + ko);
            cpa16(&As[nb][(lrow + 64) * PK + kg * 4], gA1 + ko);
            cpa16(&Bs[nb][lrow * PK + kg * 4],        gB0 + ko);
            cpa16(&Bs[nb][(lrow + 64) * PK + kg * 4], gB1 + ko);
            asm volatile("cp.async.commit_group;\n");
            asm volatile("cp.async.wait_group 1;\n");
        } else {
            asm volatile("cp.async.wait_group 0;\n");
        }
        __syncthreads();

        #pragma unroll
        for (int kk = 0; kk < BK; kk += 8) {
            unsigned a[4][4], b[4][2];
            #pragma unroll
            for (int mt = 0; mt < 4; mt++) {
                const float* p = &As[buf][(wm * 64 + mt * 16 + g) * PK + kk + tg];
                a[mt][0] = __float_as_uint(p[0]);          // (g,    tg)
                a[mt][1] = __float_as_uint(p[8 * PK]);     // (g+8,  tg)
                a[mt][2] = __float_as_uint(p[4]);          // (g,    tg+4)
                a[mt][3] = __float_as_uint(p[8 * PK + 4]); // (g+8,  tg+4)
            }
            #pragma unroll
            for (int nt = 0; nt < 4; nt++) {
                const float* q = &Bs[buf][(wn * 32 + nt * 8 + g) * PK + kk + tg];
                b[nt][0] = f2tf32(q[0]);   // (k=tg,   n=g)
                b[nt][1] = f2tf32(q[4]);   // (k=tg+4, n=g)
            }
            #pragma unroll
            for (int mt = 0; mt < 4; mt++)
                #pragma unroll
                for (int nt = 0; nt < 4; nt++) {
                    asm volatile(
                        "mma.sync.aligned.m16n8k8.row.col.f32.tf32.tf32.f32 "
                        "{%0,%1,%2,%3}, {%4,%5,%6,%7}, {%8,%9}, {%0,%1,%2,%3};"
                        : "+f"(acc[mt][nt][0]), "+f"(acc[mt][nt][1]),
                          "+f"(acc[mt][nt][2]), "+f"(acc[mt][nt][3])
                        : "r"(a[mt][0]), "r"(a[mt][1]), "r"(a[mt][2]), "r"(a[mt][3]),
                          "r"(b[nt][0]), "r"(b[nt][1]));
                }
        }
        __syncthreads();
    }

    // ---- epilogue: bias add + store (float2 pairs; V=500 even, no straddle) ----
    #pragma unroll
    for (int mt = 0; mt < 4; mt++) {
        const int r0 = m0 + wm * 64 + mt * 16 + g;
        const int r1 = r0 + 8;
        #pragma unroll
        for (int nt = 0; nt < 4; nt++) {
            const int c = v0 + wn * 32 + nt * 8 + tg * 2;
            if (c < JV) {
                const float2 bb = *(const float2*)(bias + c);
                float2 o0, o1;
                o0.x = acc[mt][nt][0] + bb.x;
                o0.y = acc[mt][nt][1] + bb.y;
                o1.x = acc[mt][nt][2] + bb.x;
                o1.y = acc[mt][nt][3] + bb.y;
                *(float2*)(out + (size_t)r0 * JV + c) = o0;
                *(float2*)(out + (size_t)r1 * JV + c) = o1;
            }
        }
    }
}

// ===========================================================================
extern "C" void kernel_launch(void* const* d_in, const int* in_sizes, int n_in,
                              void* d_out, int out_size)
{
    const float* enc  = (const float*)d_in[0];  // (8, 200, 512)
    const float* dec  = (const float*)d_in[1];  // (8, 100, 512)
    const float* W    = (const float*)d_in[2];  // (500, 512)
    const float* bias = (const float*)d_in[3];  // (500,)
    float* out = (float*)d_out;                 // (8, 200, 100, 500)

    const int tot4 = JM * (JD / 4);             // 20,480,000
    tanh_pass<<<(tot4 + 255) / 256, 256>>>(enc, dec);

    dim3 grid((JV + 127) / 128, JM / 128);      // (4, 1250)
    joiner_gemm<<<grid, 256>>>(W, bias, out);
}

// round 7
// speedup vs baseline: 1.3303x; 1.3303x over previous
#include <cuda_runtime.h>
#include <cstdint>

// Problem constants: N=8, T=200, U=100, D=512, V=500
#define JN 8
#define JT 200
#define JU 100
#define JD 512
#define JV 500
#define JM (JN * JT * JU)   // 160000

// GEMM tiling: CTA 128(M) x 128(N), BK=32 floats (128B rows, SW128), 3-stage ring
#define TM 128
#define TN 128
#define BKT 32
#define NTILE (JD / BKT)          // 16
#define NBUF 3
#define ASZ (TM * BKT * 4)        // 16384 B
#define BSZ (TN * BKT * 4)        // 16384 B
#define STAGE (ASZ + BSZ)         // 32768 B
#define DSMEM (NBUF * STAGE)      // 98304 B

// Scratch (device globals = sanctioned): A = tf32-rounded tanh(enc+dec),
// Wr = tf32-rounded W padded to 512 rows (rows 500..511 zero).
__device__ float g_A[(size_t)JM * JD];
__device__ float g_Wr[512 * 512];

// ---------------------------------------------------------------------------
__device__ __forceinline__ float fast_tanh(float x) {
    float e = __expf(2.0f * x);
    return 1.0f - __fdividef(2.0f, e + 1.0f);
}
__device__ __forceinline__ unsigned f2tf32(float f) {
    unsigned u;
    asm("cvt.rna.tf32.f32 %0, %1;" : "=r"(u) : "f"(f));
    return u;
}
__device__ __forceinline__ void cpa16(uint32_t dst, const void* src) {
    asm volatile("cp.async.cg.shared.global [%0], [%1], 16;\n" :: "r"(dst), "l"(src));
}

// ============================ Pass 1: tanh -> g_A ==========================
__global__ __launch_bounds__(256)
void tanh_pass(const float* __restrict__ enc, const float* __restrict__ dec) {
    int idx = blockIdx.x * 256 + threadIdx.x;   // one float4 of A
    const int TOT = JM * (JD / 4);              // 20,480,000
    if (idx >= TOT) return;
    int k4 = idx & 127;                         // JD/4 = 128
    int m  = idx >> 7;
    int n = m / (JT * JU);
    int r = m % (JT * JU);
    int t = r / JU;
    int u = r % JU;
    const float4 e = *(const float4*)(enc + (size_t)(n * JT + t) * JD + k4 * 4);
    const float4 d = *(const float4*)(dec + (size_t)(n * JU + u) * JD + k4 * 4);
    uint4 o;
    o.x = f2tf32(fast_tanh(e.x + d.x));
    o.y = f2tf32(fast_tanh(e.y + d.y));
    o.z = f2tf32(fast_tanh(e.z + d.z));
    o.w = f2tf32(fast_tanh(e.w + d.w));
    *(uint4*)(g_A + (size_t)m * JD + k4 * 4) = o;
}

// ======================= pre-pass: round W, pad to 512 rows ================
__global__ __launch_bounds__(256)
void prep_w(const float* __restrict__ W) {
    int idx = blockIdx.x * 256 + threadIdx.x;   // one float4 of g_Wr
    if (idx >= 512 * 128) return;
    int row = idx >> 7;
    int c4  = (idx & 127) * 4;
    uint4 o = {0u, 0u, 0u, 0u};
    if (row < JV) {
        const float4 w = *(const float4*)(W + (size_t)row * JD + c4);
        o.x = f2tf32(w.x); o.y = f2tf32(w.y); o.z = f2tf32(w.z); o.w = f2tf32(w.w);
    }
    *(uint4*)(g_Wr + (size_t)row * JD + c4) = o;
}

// ============================ Pass 2: tf32 GEMM ============================
// out[M,V] = g_A[M,K] @ g_Wr[V,K]^T + bias. 8 warps: 2(M) x 4(N), warp 64x32.
__global__ __launch_bounds__(256, 2)
void joiner_gemm(const float* __restrict__ bias, float* __restrict__ out) {
    extern __shared__ char dsm[];
    const uint32_t smem0 = (uint32_t)__cvta_generic_to_shared(dsm);

    const int tid  = threadIdx.x;
    const int lane = tid & 31;
    const int wid  = tid >> 5;
    const int g    = lane >> 2;     // 0..7
    const int tg   = lane & 3;      // 0..3
    const int wm   = wid & 1;       // warp M row (64 each)
    const int wn   = wid >> 1;      // warp N col (32 each)

    const int m0 = blockIdx.y * TM;
    const int v0 = blockIdx.x * TN;

    // ---- cp.async roles: 8 threads per row (8x16B = full 128B row) --------
    const int kg   = tid & 7;               // 16B segment within row
    const int rrow = tid >> 3;              // 0..31, rows rrow + 32*j
    const float* gAp = g_A  + (size_t)(m0 + rrow) * JD + kg * 4;
    const float* gBp = g_Wr + (size_t)(v0 + rrow) * JD + kg * 4;
    // swizzled dest offset within a tile for (row, kg)
    uint32_t dOff[4];
    #pragma unroll
    for (int j = 0; j < 4; j++) {
        const int rw = rrow + 32 * j;
        dOff[j] = (uint32_t)(rw * 128) + 16u * (uint32_t)(kg ^ (rw & 7));
    }

    // ---- ldmatrix per-lane geometry ----------------------------------------
    // lane groups 0-7 / 8-15 / 16-23 / 24-31 supply rows for matrices 0..3:
    //   mat0 = (m0-7,  k0-3), mat1 = (m8-15, k0-3),
    //   mat2 = (m0-7,  k4-7), mat3 = (m8-15, k4-7)   -> exactly {a0,a1,a2,a3}
    const int lr = (lane & 7) + 8 * ((lane >> 3) & 1);  // row within 16-row frag
    const int kh = lane >> 4;                           // k-half (0/1)
    uint32_t aOff[4], bOff[2];
    int aXk[4], bXk[2];
    #pragma unroll
    for (int mt = 0; mt < 4; mt++) {
        const int row = wm * 64 + mt * 16 + lr;
        aOff[mt] = (uint32_t)(row * 128);
        aXk[mt]  = row & 7;
    }
    #pragma unroll
    for (int pr = 0; pr < 2; pr++) {
        const int row = wn * 32 + pr * 16 + lr;
        bOff[pr] = (uint32_t)(row * 128);
        bXk[pr]  = row & 7;
    }

    float acc[4][4][4];
    #pragma unroll
    for (int mt = 0; mt < 4; mt++)
        #pragma unroll
        for (int nt = 0; nt < 4; nt++)
            #pragma unroll
            for (int i = 0; i < 4; i++) acc[mt][nt][i] = 0.0f;

    // ---- tile copy: tile p -> slot p%NBUF ----------------------------------
    auto issue_copy = [&](int p) {
        const uint32_t ab = smem0 + (uint32_t)((p % NBUF) * STAGE);
        const uint32_t bb = ab + ASZ;
        const int ko = p * BKT;
        #pragma unroll
        for (int j = 0; j < 4; j++) {
            cpa16(ab + dOff[j], gAp + (size_t)(32 * j) * JD + ko);
            cpa16(bb + dOff[j], gBp + (size_t)(32 * j) * JD + ko);
        }
        asm volatile("cp.async.commit_group;");
    };

    // prologue
    #pragma unroll
    for (int p = 0; p < NBUF - 1; p++) issue_copy(p);

    #pragma unroll 1
    for (int it = 0; it < NTILE; ++it) {
        asm volatile("cp.async.wait_group %0;" :: "n"(NBUF - 2));
        __syncthreads();
        if (it + NBUF - 1 < NTILE) issue_copy(it + NBUF - 1);

        const uint32_t ab = smem0 + (uint32_t)((it % NBUF) * STAGE);
        const uint32_t bb = ab + ASZ;

        #pragma unroll
        for (int ks = 0; ks < BKT / 8; ks++) {       // 4 k8 slices
            unsigned a[4][4], b[4][2];
            const int ksk = (ks << 1) | kh;
            #pragma unroll
            for (int mt = 0; mt < 4; mt++) {
                const uint32_t ad = ab + aOff[mt] + 16u * (uint32_t)(ksk ^ aXk[mt]);
                asm volatile("ldmatrix.sync.aligned.m8n8.x4.shared.b16 {%0,%1,%2,%3}, [%4];"
                             : "=r"(a[mt][0]), "=r"(a[mt][1]), "=r"(a[mt][2]), "=r"(a[mt][3])
                             : "r"(ad));
            }
            #pragma unroll
            for (int pr = 0; pr < 2; pr++) {
                const uint32_t bd = bb + bOff[pr] + 16u * (uint32_t)(ksk ^ bXk[pr]);
                unsigned r0, r1, r2, r3;
                asm volatile("ldmatrix.sync.aligned.m8n8.x4.shared.b16 {%0,%1,%2,%3}, [%4];"
                             : "=r"(r0), "=r"(r1), "=r"(r2), "=r"(r3) : "r"(bd));
                b[pr * 2 + 0][0] = r0;  b[pr * 2 + 1][0] = r1;
                b[pr * 2 + 0][1] = r2;  b[pr * 2 + 1][1] = r3;
            }
            #pragma unroll
            for (int mt = 0; mt < 4; mt++)
                #pragma unroll
                for (int nt = 0; nt < 4; nt++) {
                    asm volatile(
                        "mma.sync.aligned.m16n8k8.row.col.f32.tf32.tf32.f32 "
                        "{%0,%1,%2,%3}, {%4,%5,%6,%7}, {%8,%9}, {%0,%1,%2,%3};"
                        : "+f"(acc[mt][nt][0]), "+f"(acc[mt][nt][1]),
                          "+f"(acc[mt][nt][2]), "+f"(acc[mt][nt][3])
                        : "r"(a[mt][0]), "r"(a[mt][1]), "r"(a[mt][2]), "r"(a[mt][3]),
                          "r"(b[nt][0]), "r"(b[nt][1]));
                }
        }
    }

    // ---- epilogue: bias + float2 stores ------------------------------------
    #pragma unroll
    for (int mt = 0; mt < 4; mt++) {
        const int r0 = m0 + wm * 64 + mt * 16 + g;
        const int r1 = r0 + 8;
        #pragma unroll
        for (int nt = 0; nt < 4; nt++) {
            const int c = v0 + wn * 32 + nt * 8 + tg * 2;
            if (c < JV) {
                const float2 bb2 = *(const float2*)(bias + c);
                float2 o0, o1;
                o0.x = acc[mt][nt][0] + bb2.x;
                o0.y = acc[mt][nt][1] + bb2.y;
                o1.x = acc[mt][nt][2] + bb2.x;
                o1.y = acc[mt][nt][3] + bb2.y;
                *(float2*)(out + (size_t)r0 * JV + c) = o0;
                *(float2*)(out + (size_t)r1 * JV + c) = o1;
            }
        }
    }
}

// ===========================================================================
extern "C" void kernel_launch(void* const* d_in, const int* in_sizes, int n_in,
                              void* d_out, int out_size)
{
    const float* enc  = (const float*)d_in[0];  // (8, 200, 512)
    const float* dec  = (const float*)d_in[1];  // (8, 100, 512)
    const float* W    = (const float*)d_in[2];  // (500, 512)
    const float* bias = (const float*)d_in[3];  // (500,)
    float* out = (float*)d_out;                 // (8, 200, 100, 500)

    prep_w<<<256, 256>>>(W);
    tanh_pass<<<(JM * (JD / 4) + 255) / 256, 256>>>(enc, dec);

    cudaFuncSetAttribute(joiner_gemm, cudaFuncAttributeMaxDynamicSharedMemorySize, DSMEM);
    dim3 grid(4, JM / TM);                      // (4, 1250)
    joiner_gemm<<<grid, 256, DSMEM>>>(bias, out);
}

// round 8
// speedup vs baseline: 1.3364x; 1.0046x over previous
#include <cuda_runtime.h>
#include <cstdint>

// Problem constants: N=8, T=200, U=100, D=512, V=500
#define JN 8
#define JT 200
#define JU 100
#define JD 512
#define JV 500
#define JM (JN * JT * JU)   // 160000

// GEMM tiling: CTA 128(M) x 128(N), BK=32 floats (128B rows, SW128), 3-stage ring
#define TM 128
#define TN 128
#define BKT 32
#define NTILE (JD / BKT)          // 16
#define NBUF 3
#define ASZ (TM * BKT * 4)        // 16384 B
#define BSZ (TN * BKT * 4)        // 16384 B
#define STAGE (ASZ + BSZ)         // 32768 B
#define DSMEM (NBUF * STAGE)      // 98304 B

// Scratch (device globals = sanctioned): A = tf32-rounded tanh(enc+dec),
// Wr = tf32-rounded W padded to 512 rows (rows 500..511 zero).
__device__ float g_A[(size_t)JM * JD];
__device__ float g_Wr[512 * 512];

// ---------------------------------------------------------------------------
__device__ __forceinline__ float fast_tanh(float x) {
    float e = __expf(2.0f * x);
    return 1.0f - __fdividef(2.0f, e + 1.0f);
}
__device__ __forceinline__ unsigned f2tf32(float f) {
    unsigned u;
    asm("cvt.rna.tf32.f32 %0, %1;" : "=r"(u) : "f"(f));
    return u;
}
__device__ __forceinline__ void cpa16(uint32_t dst, const void* src) {
    asm volatile("cp.async.cg.shared.global [%0], [%1], 16;\n" :: "r"(dst), "l"(src));
}

// ============================ Pass 1: tanh -> g_A ==========================
__global__ __launch_bounds__(256)
void tanh_pass(const float* __restrict__ enc, const float* __restrict__ dec) {
    int idx = blockIdx.x * 256 + threadIdx.x;   // one float4 of A
    const int TOT = JM * (JD / 4);              // 20,480,000
    if (idx >= TOT) return;
    int k4 = idx & 127;                         // JD/4 = 128
    int m  = idx >> 7;
    int n = m / (JT * JU);
    int r = m % (JT * JU);
    int t = r / JU;
    int u = r % JU;
    const float4 e = *(const float4*)(enc + (size_t)(n * JT + t) * JD + k4 * 4);
    const float4 d = *(const float4*)(dec + (size_t)(n * JU + u) * JD + k4 * 4);
    uint4 o;
    o.x = f2tf32(fast_tanh(e.x + d.x));
    o.y = f2tf32(fast_tanh(e.y + d.y));
    o.z = f2tf32(fast_tanh(e.z + d.z));
    o.w = f2tf32(fast_tanh(e.w + d.w));
    *(uint4*)(g_A + (size_t)m * JD + k4 * 4) = o;
}

// ======================= pre-pass: round W, pad to 512 rows ================
__global__ __launch_bounds__(256)
void prep_w(const float* __restrict__ W) {
    int idx = blockIdx.x * 256 + threadIdx.x;   // one float4 of g_Wr
    if (idx >= 512 * 128) return;
    int row = idx >> 7;
    int c4  = (idx & 127) * 4;
    uint4 o = {0u, 0u, 0u, 0u};
    if (row < JV) {
        const float4 w = *(const float4*)(W + (size_t)row * JD + c4);
        o.x = f2tf32(w.x); o.y = f2tf32(w.y); o.z = f2tf32(w.z); o.w = f2tf32(w.w);
    }
    *(uint4*)(g_Wr + (size_t)row * JD + c4) = o;
}

// ============================ Pass 2: tf32 GEMM ============================
// out[M,V] = g_A[M,K] @ g_Wr[V,K]^T + bias. 8 warps: 2(M) x 4(N), warp 64x32.
// Fragment double-buffering: slice s+1's LDSMs issue before slice s's HMMAs.
__global__ __launch_bounds__(256, 2)
void joiner_gemm(const float* __restrict__ bias, float* __restrict__ out) {
    extern __shared__ char dsm[];
    const uint32_t smem0 = (uint32_t)__cvta_generic_to_shared(dsm);

    const int tid  = threadIdx.x;
    const int lane = tid & 31;
    const int wid  = tid >> 5;
    const int g    = lane >> 2;     // 0..7
    const int tg   = lane & 3;      // 0..3
    const int wm   = wid & 1;       // warp M row (64 each)
    const int wn   = wid >> 1;      // warp N col (32 each)

    const int m0 = blockIdx.y * TM;
    const int v0 = blockIdx.x * TN;

    // ---- cp.async roles: 8 threads per row (8x16B = full 128B row) --------
    const int kg   = tid & 7;               // 16B segment within row
    const int rrow = tid >> 3;              // 0..31, rows rrow + 32*j
    const float* gAp = g_A  + (size_t)(m0 + rrow) * JD + kg * 4;
    const float* gBp = g_Wr + (size_t)(v0 + rrow) * JD + kg * 4;
    // swizzled dest offset within a tile for (row, kg)
    uint32_t dOff[4];
    #pragma unroll
    for (int j = 0; j < 4; j++) {
        const int rw = rrow + 32 * j;
        dOff[j] = (uint32_t)(rw * 128) + 16u * (uint32_t)(kg ^ (rw & 7));
    }

    // ---- ldmatrix per-lane geometry ----------------------------------------
    // lane groups 0-7 / 8-15 / 16-23 / 24-31 supply rows for matrices 0..3:
    //   mat0 = (m0-7,  k0-3), mat1 = (m8-15, k0-3),
    //   mat2 = (m0-7,  k4-7), mat3 = (m8-15, k4-7)   -> exactly {a0,a1,a2,a3}
    const int lr = (lane & 7) + 8 * ((lane >> 3) & 1);  // row within 16-row frag
    const int kh = lane >> 4;                           // k-half (0/1)
    uint32_t aOff[4], bOff[2];
    int aXk[4], bXk[2];
    #pragma unroll
    for (int mt = 0; mt < 4; mt++) {
        const int row = wm * 64 + mt * 16 + lr;
        aOff[mt] = (uint32_t)(row * 128);
        aXk[mt]  = row & 7;
    }
    #pragma unroll
    for (int pr = 0; pr < 2; pr++) {
        const int row = wn * 32 + pr * 16 + lr;
        bOff[pr] = (uint32_t)(row * 128);
        bXk[pr]  = row & 7;
    }

    float acc[4][4][4];
    #pragma unroll
    for (int mt = 0; mt < 4; mt++)
        #pragma unroll
        for (int nt = 0; nt < 4; nt++)
            #pragma unroll
            for (int i = 0; i < 4; i++) acc[mt][nt][i] = 0.0f;

    // ---- tile copy: tile p -> slot p%NBUF ----------------------------------
    auto issue_copy = [&](int p) {
        const uint32_t ab = smem0 + (uint32_t)((p % NBUF) * STAGE);
        const uint32_t bb = ab + ASZ;
        const int ko = p * BKT;
        #pragma unroll
        for (int j = 0; j < 4; j++) {
            cpa16(ab + dOff[j], gAp + (size_t)(32 * j) * JD + ko);
            cpa16(bb + dOff[j], gBp + (size_t)(32 * j) * JD + ko);
        }
        asm volatile("cp.async.commit_group;");
    };

    // ---- fragment load for one k8 slice ------------------------------------
    auto load_frags = [&](uint32_t ab, uint32_t bb, int ks,
                          unsigned (*a)[4], unsigned (*b)[2]) {
        const int ksk = (ks << 1) | kh;
        #pragma unroll
        for (int mt = 0; mt < 4; mt++) {
            const uint32_t ad = ab + aOff[mt] + 16u * (uint32_t)(ksk ^ aXk[mt]);
            asm volatile("ldmatrix.sync.aligned.m8n8.x4.shared.b16 {%0,%1,%2,%3}, [%4];"
                         : "=r"(a[mt][0]), "=r"(a[mt][1]), "=r"(a[mt][2]), "=r"(a[mt][3])
                         : "r"(ad));
        }
        #pragma unroll
        for (int pr = 0; pr < 2; pr++) {
            const uint32_t bd = bb + bOff[pr] + 16u * (uint32_t)(ksk ^ bXk[pr]);
            unsigned r0, r1, r2, r3;
            asm volatile("ldmatrix.sync.aligned.m8n8.x4.shared.b16 {%0,%1,%2,%3}, [%4];"
                         : "=r"(r0), "=r"(r1), "=r"(r2), "=r"(r3) : "r"(bd));
            b[pr * 2 + 0][0] = r0;  b[pr * 2 + 1][0] = r1;
            b[pr * 2 + 0][1] = r2;  b[pr * 2 + 1][1] = r3;
        }
    };

    unsigned aF[2][4][4], bF[2][4][2];

    // prologue
    #pragma unroll
    for (int p = 0; p < NBUF - 1; p++) issue_copy(p);

    #pragma unroll 1
    for (int it = 0; it < NTILE; ++it) {
        asm volatile("cp.async.wait_group %0;" :: "n"(NBUF - 2));
        __syncthreads();
        if (it + NBUF - 1 < NTILE) issue_copy(it + NBUF - 1);

        const uint32_t ab = smem0 + (uint32_t)((it % NBUF) * STAGE);
        const uint32_t bb = ab + ASZ;

        load_frags(ab, bb, 0, aF[0], bF[0]);     // preload slice 0

        #pragma unroll
        for (int ks = 0; ks < BKT / 8; ks++) {   // 4 k8 slices
            const int cur = ks & 1;
            if (ks < BKT / 8 - 1)
                load_frags(ab, bb, ks + 1, aF[cur ^ 1], bF[cur ^ 1]);
            #pragma unroll
            for (int mt = 0; mt < 4; mt++)
                #pragma unroll
                for (int nt = 0; nt < 4; nt++) {
                    asm volatile(
                        "mma.sync.aligned.m16n8k8.row.col.f32.tf32.tf32.f32 "
                        "{%0,%1,%2,%3}, {%4,%5,%6,%7}, {%8,%9}, {%0,%1,%2,%3};"
                        : "+f"(acc[mt][nt][0]), "+f"(acc[mt][nt][1]),
                          "+f"(acc[mt][nt][2]), "+f"(acc[mt][nt][3])
                        : "r"(aF[cur][mt][0]), "r"(aF[cur][mt][1]),
                          "r"(aF[cur][mt][2]), "r"(aF[cur][mt][3]),
                          "r"(bF[cur][nt][0]), "r"(bF[cur][nt][1]));
                }
        }
    }

    // ---- epilogue: bias + float2 stores ------------------------------------
    #pragma unroll
    for (int mt = 0; mt < 4; mt++) {
        const int r0 = m0 + wm * 64 + mt * 16 + g;
        const int r1 = r0 + 8;
        #pragma unroll
        for (int nt = 0; nt < 4; nt++) {
            const int c = v0 + wn * 32 + nt * 8 + tg * 2;
            if (c < JV) {
                const float2 bb2 = *(const float2*)(bias + c);
                float2 o0, o1;
                o0.x = acc[mt][nt][0] + bb2.x;
                o0.y = acc[mt][nt][1] + bb2.y;
                o1.x = acc[mt][nt][2] + bb2.x;
                o1.y = acc[mt][nt][3] + bb2.y;
                *(float2*)(out + (size_t)r0 * JV + c) = o0;
                *(float2*)(out + (size_t)r1 * JV + c) = o1;
            }
        }
    }
}

// ===========================================================================
extern "C" void kernel_launch(void* const* d_in, const int* in_sizes, int n_in,
                              void* d_out, int out_size)
{
    const float* enc  = (const float*)d_in[0];  // (8, 200, 512)
    const float* dec  = (const float*)d_in[1];  // (8, 100, 512)
    const float* W    = (const float*)d_in[2];  // (500, 512)
    const float* bias = (const float*)d_in[3];  // (500,)
    float* out = (float*)d_out;                 // (8, 200, 100, 500)

    prep_w<<<256, 256>>>(W);
    tanh_pass<<<(JM * (JD / 4) + 255) / 256, 256>>>(enc, dec);

    cudaFuncSetAttribute(joiner_gemm, cudaFuncAttributeMaxDynamicSharedMemorySize, DSMEM);
    dim3 grid(4, JM / TM);                      // (4, 1250)
    joiner_gemm<<<grid, 256, DSMEM>>>(bias, out);
}

// round 9
// speedup vs baseline: 2.3494x; 1.7580x over previous
#include <cuda_runtime.h>
#include <cuda_fp16.h>
#include <cstdint>

// Problem constants: N=8, T=200, U=100, D=512, V=500
#define JN 8
#define JT 200
#define JU 100
#define JD 512
#define JV 500
#define JM (JN * JT * JU)   // 160000

// GEMM tiling: CTA 128(M) x 128(N), BK=64 fp16 (128B rows, SW128), 3-stage ring
#define TM 128
#define TN 128
#define BKT 64
#define NTILE (JD / BKT)          // 8
#define NBUF 3
#define ASZ (TM * BKT * 2)        // 16384 B
#define BSZ (TN * BKT * 2)        // 16384 B
#define STAGE (ASZ + BSZ)         // 32768 B
#define DSMEM (NBUF * STAGE)      // 98304 B

// Scratch (device globals = sanctioned): A = fp16 tanh(enc+dec),
// Wh = fp16 W padded to 512 rows (rows 500..511 zero).
__device__ __half g_A[(size_t)JM * JD];
__device__ __half g_Wh[512 * 512];

// ---------------------------------------------------------------------------
__device__ __forceinline__ float fast_tanh(float x) {
    float e = __expf(2.0f * x);
    return 1.0f - __fdividef(2.0f, e + 1.0f);
}
__device__ __forceinline__ void cpa16(uint32_t dst, const void* src) {
    asm volatile("cp.async.cg.shared.global [%0], [%1], 16;\n" :: "r"(dst), "l"(src));
}

// ============================ Pass 1: tanh -> g_A (fp16) ===================
__global__ __launch_bounds__(256)
void tanh_pass(const float* __restrict__ enc, const float* __restrict__ dec) {
    int idx = blockIdx.x * 256 + threadIdx.x;   // one 16B chunk = 8 fp16
    const int TOT = JM * (JD / 8);              // 10,240,000
    if (idx >= TOT) return;
    int k8 = idx & 63;                          // JD/8 = 64
    int m  = idx >> 6;
    int n = m / (JT * JU);
    int r = m % (JT * JU);
    int t = r / JU;
    int u = r % JU;
    const float4* ep = (const float4*)(enc + (size_t)(n * JT + t) * JD + k8 * 8);
    const float4* dp = (const float4*)(dec + (size_t)(n * JU + u) * JD + k8 * 8);
    const float4 e0 = ep[0], e1 = ep[1];
    const float4 d0 = dp[0], d1 = dp[1];
    __half2 h[4];
    h[0] = __floats2half2_rn(fast_tanh(e0.x + d0.x), fast_tanh(e0.y + d0.y));
    h[1] = __floats2half2_rn(fast_tanh(e0.z + d0.z), fast_tanh(e0.w + d0.w));
    h[2] = __floats2half2_rn(fast_tanh(e1.x + d1.x), fast_tanh(e1.y + d1.y));
    h[3] = __floats2half2_rn(fast_tanh(e1.z + d1.z), fast_tanh(e1.w + d1.w));
    *(uint4*)(g_A + (size_t)m * JD + k8 * 8) = *(const uint4*)h;
}

// ======================= pre-pass: W -> fp16, pad to 512 rows ==============
__global__ __launch_bounds__(256)
void prep_w(const float* __restrict__ W) {
    int idx = blockIdx.x * 256 + threadIdx.x;   // one 16B chunk = 8 fp16
    if (idx >= 512 * 64) return;                // 512 rows x 64 chunks
    int row = idx >> 6;
    int c8  = (idx & 63) * 8;
    __half2 h[4] = {__half2{}, __half2{}, __half2{}, __half2{}};
    if (row < JV) {
        const float4* wp = (const float4*)(W + (size_t)row * JD + c8);
        const float4 w0 = wp[0], w1 = wp[1];
        h[0] = __floats2half2_rn(w0.x, w0.y);
        h[1] = __floats2half2_rn(w0.z, w0.w);
        h[2] = __floats2half2_rn(w1.x, w1.y);
        h[3] = __floats2half2_rn(w1.z, w1.w);
    }
    *(uint4*)(g_Wh + (size_t)row * JD + c8) = *(const uint4*)h;
}

// ============================ Pass 2: fp16 GEMM ============================
// out[M,V] = g_A[M,K] @ g_Wh[V,K]^T + bias. 8 warps: 2(M) x 4(N), warp 64x32.
// mma.m16n8k16.f16 with fp32 accumulate; ldmatrix fragment feed, SW128.
__global__ __launch_bounds__(256, 2)
void joiner_gemm(const float* __restrict__ bias, float* __restrict__ out) {
    extern __shared__ char dsm[];
    const uint32_t smem0 = (uint32_t)__cvta_generic_to_shared(dsm);

    const int tid  = threadIdx.x;
    const int lane = tid & 31;
    const int wid  = tid >> 5;
    const int g    = lane >> 2;     // 0..7
    const int tg   = lane & 3;      // 0..3
    const int wm   = wid & 1;       // warp M row (64 each)
    const int wn   = wid >> 1;      // warp N col (32 each)

    const int m0 = blockIdx.y * TM;
    const int v0 = blockIdx.x * TN;

    // ---- cp.async roles: 8 threads per row (8x16B = full 128B row) --------
    const int kg   = tid & 7;               // 16B segment within row (8 fp16)
    const int rrow = tid >> 3;              // 0..31, rows rrow + 32*j
    const __half* gAp = g_A  + (size_t)(m0 + rrow) * JD + kg * 8;
    const __half* gBp = g_Wh + (size_t)(v0 + rrow) * JD + kg * 8;
    uint32_t dOff[4];
    #pragma unroll
    for (int j = 0; j < 4; j++) {
        const int rw = rrow + 32 * j;
        dOff[j] = (uint32_t)(rw * 128) + 16u * (uint32_t)(kg ^ (rw & 7));
    }

    // ---- ldmatrix per-lane geometry ----------------------------------------
    // x4 matrices: mat0 = rows 0-7 seg even, mat1 = rows 8-15 seg even,
    //              mat2 = rows 0-7 seg odd,  mat3 = rows 8-15 seg odd
    // -> exactly the m16n8k16 {a0..a3} fragment (k0-7 / k8-15 halves).
    const int lr = (lane & 7) + 8 * ((lane >> 3) & 1);  // row within 16-row frag
    const int kh = lane >> 4;                           // k-half (0/1)
    uint32_t aOff[4], bOff[2];
    int aXk[4], bXk[2];
    #pragma unroll
    for (int mt = 0; mt < 4; mt++) {
        const int row = wm * 64 + mt * 16 + lr;
        aOff[mt] = (uint32_t)(row * 128);
        aXk[mt]  = row & 7;
    }
    #pragma unroll
    for (int pr = 0; pr < 2; pr++) {
        const int row = wn * 32 + pr * 16 + lr;
        bOff[pr] = (uint32_t)(row * 128);
        bXk[pr]  = row & 7;
    }

    float acc[4][4][4];
    #pragma unroll
    for (int mt = 0; mt < 4; mt++)
        #pragma unroll
        for (int nt = 0; nt < 4; nt++)
            #pragma unroll
            for (int i = 0; i < 4; i++) acc[mt][nt][i] = 0.0f;

    // ---- tile copy: tile p -> slot p%NBUF ----------------------------------
    auto issue_copy = [&](int p) {
        const uint32_t ab = smem0 + (uint32_t)((p % NBUF) * STAGE);
        const uint32_t bb = ab + ASZ;
        const int ko = p * BKT;
        #pragma unroll
        for (int j = 0; j < 4; j++) {
            cpa16(ab + dOff[j], gAp + (size_t)(32 * j) * JD + ko);
            cpa16(bb + dOff[j], gBp + (size_t)(32 * j) * JD + ko);
        }
        asm volatile("cp.async.commit_group;");
    };

    // ---- fragment load for one k16 slice (= 32B = 2 segs) ------------------
    auto load_frags = [&](uint32_t ab, uint32_t bb, int ks,
                          unsigned (*a)[4], unsigned (*b)[2]) {
        const int ksk = (ks << 1) | kh;
        #pragma unroll
        for (int mt = 0; mt < 4; mt++) {
            const uint32_t ad = ab + aOff[mt] + 16u * (uint32_t)(ksk ^ aXk[mt]);
            asm volatile("ldmatrix.sync.aligned.m8n8.x4.shared.b16 {%0,%1,%2,%3}, [%4];"
                         : "=r"(a[mt][0]), "=r"(a[mt][1]), "=r"(a[mt][2]), "=r"(a[mt][3])
                         : "r"(ad));
        }
        #pragma unroll
        for (int pr = 0; pr < 2; pr++) {
            const uint32_t bd = bb + bOff[pr] + 16u * (uint32_t)(ksk ^ bXk[pr]);
            unsigned r0, r1, r2, r3;
            asm volatile("ldmatrix.sync.aligned.m8n8.x4.shared.b16 {%0,%1,%2,%3}, [%4];"
                         : "=r"(r0), "=r"(r1), "=r"(r2), "=r"(r3) : "r"(bd));
            b[pr * 2 + 0][0] = r0;  b[pr * 2 + 1][0] = r1;
            b[pr * 2 + 0][1] = r2;  b[pr * 2 + 1][1] = r3;
        }
    };

    unsigned aF[2][4][4], bF[2][4][2];

    // prologue
    #pragma unroll
    for (int p = 0; p < NBUF - 1; p++) issue_copy(p);

    #pragma unroll 1
    for (int it = 0; it < NTILE; ++it) {
        asm volatile("cp.async.wait_group %0;" :: "n"(NBUF - 2));
        __syncthreads();
        if (it + NBUF - 1 < NTILE) issue_copy(it + NBUF - 1);

        const uint32_t ab = smem0 + (uint32_t)((it % NBUF) * STAGE);
        const uint32_t bb = ab + ASZ;

        load_frags(ab, bb, 0, aF[0], bF[0]);     // preload slice 0

        #pragma unroll
        for (int ks = 0; ks < BKT / 16; ks++) {  // 4 k16 slices
            const int cur = ks & 1;
            if (ks < BKT / 16 - 1)
                load_frags(ab, bb, ks + 1, aF[cur ^ 1], bF[cur ^ 1]);
            #pragma unroll
            for (int mt = 0; mt < 4; mt++)
                #pragma unroll
                for (int nt = 0; nt < 4; nt++) {
                    asm volatile(
                        "mma.sync.aligned.m16n8k16.row.col.f32.f16.f16.f32 "
                        "{%0,%1,%2,%3}, {%4,%5,%6,%7}, {%8,%9}, {%0,%1,%2,%3};"
                        : "+f"(acc[mt][nt][0]), "+f"(acc[mt][nt][1]),
                          "+f"(acc[mt][nt][2]), "+f"(acc[mt][nt][3])
                        : "r"(aF[cur][mt][0]), "r"(aF[cur][mt][1]),
                          "r"(aF[cur][mt][2]), "r"(aF[cur][mt][3]),
                          "r"(bF[cur][nt][0]), "r"(bF[cur][nt][1]));
                }
        }
    }

    // ---- epilogue: bias + float2 stores ------------------------------------
    #pragma unroll
    for (int mt = 0; mt < 4; mt++) {
        const int r0 = m0 + wm * 64 + mt * 16 + g;
        const int r1 = r0 + 8;
        #pragma unroll
        for (int nt = 0; nt < 4; nt++) {
            const int c = v0 + wn * 32 + nt * 8 + tg * 2;
            if (c < JV) {
                const float2 bb2 = *(const float2*)(bias + c);
                float2 o0, o1;
                o0.x = acc[mt][nt][0] + bb2.x;
                o0.y = acc[mt][nt][1] + bb2.y;
                o1.x = acc[mt][nt][2] + bb2.x;
                o1.y = acc[mt][nt][3] + bb2.y;
                *(float2*)(out + (size_t)r0 * JV + c) = o0;
                *(float2*)(out + (size_t)r1 * JV + c) = o1;
            }
        }
    }
}

// ===========================================================================
extern "C" void kernel_launch(void* const* d_in, const int* in_sizes, int n_in,
                              void* d_out, int out_size)
{
    const float* enc  = (const float*)d_in[0];  // (8, 200, 512)
    const float* dec  = (const float*)d_in[1];  // (8, 100, 512)
    const float* W    = (const float*)d_in[2];  // (500, 512)
    const float* bias = (const float*)d_in[3];  // (500,)
    float* out = (float*)d_out;                 // (8, 200, 100, 500)

    prep_w<<<128, 256>>>(W);
    tanh_pass<<<(JM * (JD / 8) + 255) / 256, 256>>>(enc, dec);

    cudaFuncSetAttribute(joiner_gemm, cudaFuncAttributeMaxDynamicSharedMemorySize, DSMEM);
    dim3 grid(4, JM / TM);                      // (4, 1250)
    joiner_gemm<<<grid, 256, DSMEM>>>(bias, out);
}